// round 6
// baseline (speedup 1.0000x reference)
#include <cuda_runtime.h>
#include <cuda_fp16.h>

#define N_NODES 100000
#define N_EDGES 1600000
#define D_IN    480
#define D_OUT   256
#define NEG_SLOPE 0.2f

// ---------------- scratch ----------------
__device__ float g_xl[(size_t)N_NODES * D_OUT];
__device__ float g_xr[(size_t)N_NODES * D_OUT];
__device__ int   g_counts[N_NODES];
__device__ int   g_offs[N_NODES];
__device__ int   g_wpos[N_NODES];
__device__ int   g_csrc[N_EDGES];
__device__ int   g_bsum[128];
__device__ int   g_bsum_ex[128];

// pack two fp32 -> one uint holding half2 (single SASS instruction)
__device__ __forceinline__ unsigned pack_half2(float lo, float hi) {
    unsigned r;
    asm("cvt.rn.f16x2.f32 %0, %1, %2;" : "=r"(r) : "f"(hi), "f"(lo));
    return r;
}

// ---------------- K0: init ----------------
__global__ void init_kernel() {
    int i = blockIdx.x * blockDim.x + threadIdx.x;
    if (i < N_NODES) g_counts[i] = 0;
}

// ---------------- K2: dst histogram ----------------
__global__ void hist_kernel(const int* __restrict__ ei) {
    int e = blockIdx.x * blockDim.x + threadIdx.x;
    if (e < N_EDGES) atomicAdd(&g_counts[ei[N_EDGES + e]], 1);
}

// ---------------- K1: pipelined dual GEMM via fp16 mma.m16n8k16 ----------------
// Combined col space [0,512): [0,256)->W_l->g_xl ; [256,512)->W_r->g_xr
// Block 128x128, BK=32, 2-stage. 8 warps, each 32(m) x 64(n).
// A smem: [m][k] halves, row stride 40 halves (20 uint) -> conflict-free frags.
// B smem: transposed [n][k] halves, same stride.
#define GBM 128
#define GBN 128
#define GBK 32
#define SROW 20            // row stride in uint (half2) units = 40 halves
#define NIT (D_IN / GBK)   // 15

__global__ __launch_bounds__(256, 2)
void gemm_fp16_kernel(const float* __restrict__ X,
                      const float* __restrict__ W_l, const float* __restrict__ b_l,
                      const float* __restrict__ W_r, const float* __restrict__ b_r) {
    __shared__ unsigned As[2][GBM * SROW];   // half2-packed
    __shared__ unsigned Bt[2][GBN * SROW];   // transposed, half2-packed (k-pairs)

    int tx   = threadIdx.x;
    int lane = tx & 31;
    int wid  = tx >> 5;
    int warp_m = wid & 3;
    int warp_n = wid >> 2;
    int gid = lane >> 2;   // 0..7
    int tg  = lane & 3;    // 0..3

    int row0 = blockIdx.y * GBM;
    int col0 = blockIdx.x * GBN;

    const float* W; const float* bv; float* Y;
    int wc = col0;
    if (col0 < D_OUT) { W = W_l; bv = b_l; Y = g_xl; }
    else              { W = W_r; bv = b_r; Y = g_xr; wc = col0 - D_OUT; }

    // A loader: 4 float4/thread. f = tx: m = f>>3 (0..31)+i*32, kq = f&7
    int am  = tx >> 3;
    int akq = tx & 7;
    // B loader: 2 assignments/thread. kp = tx&15 (k-pair), nq = tx>>4 (n-quad)
    int bkp = tx & 15;
    int bnq = tx >> 4;

    float4 ra[4];
    float4 rb[2][2];

    auto loadG = [&](int it) {
        int k0 = it * GBK;
#pragma unroll
        for (int i = 0; i < 4; i++) {
            int m  = am + i * 32;
            int gr = row0 + m;
            float4 v = make_float4(0.f, 0.f, 0.f, 0.f);
            if (gr < N_NODES)
                v = *reinterpret_cast<const float4*>(X + (size_t)gr * D_IN + k0 + akq * 4);
            ra[i] = v;
        }
#pragma unroll
        for (int i = 0; i < 2; i++) {
            int kp = bkp;
            int nq = bnq + i * 16;
            rb[i][0] = *reinterpret_cast<const float4*>(W + (size_t)(k0 + 2 * kp) * D_OUT + wc + nq * 4);
            rb[i][1] = *reinterpret_cast<const float4*>(W + (size_t)(k0 + 2 * kp + 1) * D_OUT + wc + nq * 4);
        }
    };
    auto storeS = [&](int buf) {
#pragma unroll
        for (int i = 0; i < 4; i++) {
            int m = am + i * 32;
            float4 v = ra[i];
            unsigned h01 = pack_half2(v.x, v.y);
            unsigned h23 = pack_half2(v.z, v.w);
            *reinterpret_cast<uint2*>(&As[buf][m * SROW + akq * 2]) = make_uint2(h01, h23);
        }
#pragma unroll
        for (int i = 0; i < 2; i++) {
            int kp = bkp;
            int nq = bnq + i * 16;
            const float* lo = &rb[i][0].x;
            const float* hi = &rb[i][1].x;
#pragma unroll
            for (int j = 0; j < 4; j++) {
                Bt[buf][(nq * 4 + j) * SROW + kp] = pack_half2(lo[j], hi[j]);
            }
        }
    };

    float acc[2][8][4];
#pragma unroll
    for (int mt = 0; mt < 2; mt++)
#pragma unroll
        for (int nt = 0; nt < 8; nt++)
#pragma unroll
            for (int i = 0; i < 4; i++) acc[mt][nt][i] = 0.f;

    loadG(0);
    storeS(0);
    __syncthreads();

    for (int it = 0; it < NIT; it++) {
        int cur = it & 1;
        if (it + 1 < NIT) loadG(it + 1);

#pragma unroll
        for (int ks = 0; ks < 2; ks++) {
            int ko = ks * 8;     // uint offset for this k16 half
            unsigned a[2][4];
#pragma unroll
            for (int mt = 0; mt < 2; mt++) {
                int r = warp_m * 32 + mt * 16 + gid;
                a[mt][0] = As[cur][r * SROW + ko + tg];
                a[mt][1] = As[cur][(r + 8) * SROW + ko + tg];
                a[mt][2] = As[cur][r * SROW + ko + tg + 4];
                a[mt][3] = As[cur][(r + 8) * SROW + ko + tg + 4];
            }
#pragma unroll
            for (int nt = 0; nt < 8; nt++) {
                int n = warp_n * 64 + nt * 8 + gid;
                unsigned b0 = Bt[cur][n * SROW + ko + tg];
                unsigned b1 = Bt[cur][n * SROW + ko + tg + 4];
#pragma unroll
                for (int mt = 0; mt < 2; mt++) {
                    asm volatile(
                        "mma.sync.aligned.m16n8k16.row.col.f32.f16.f16.f32 "
                        "{%0,%1,%2,%3}, {%4,%5,%6,%7}, {%8,%9}, {%0,%1,%2,%3};"
                        : "+f"(acc[mt][nt][0]), "+f"(acc[mt][nt][1]),
                          "+f"(acc[mt][nt][2]), "+f"(acc[mt][nt][3])
                        : "r"(a[mt][0]), "r"(a[mt][1]), "r"(a[mt][2]), "r"(a[mt][3]),
                          "r"(b0), "r"(b1));
                }
            }
        }

        if (it + 1 < NIT) storeS((it + 1) & 1);
        __syncthreads();
    }

#pragma unroll
    for (int mt = 0; mt < 2; mt++) {
        int r = row0 + warp_m * 32 + mt * 16 + gid;
#pragma unroll
        for (int nt = 0; nt < 8; nt++) {
            int c = wc + warp_n * 64 + nt * 8 + tg * 2;
            if (r < N_NODES) {
                float2 v;
                v.x = acc[mt][nt][0] + bv[c];
                v.y = acc[mt][nt][1] + bv[c + 1];
                *reinterpret_cast<float2*>(Y + (size_t)r * D_OUT + c) = v;
            }
            if (r + 8 < N_NODES) {
                float2 v;
                v.x = acc[mt][nt][2] + bv[c];
                v.y = acc[mt][nt][3] + bv[c + 1];
                *reinterpret_cast<float2*>(Y + (size_t)(r + 8) * D_OUT + c) = v;
            }
        }
    }
}

// ---------------- K3: exclusive scan ----------------
#define SCAN_CH 1024
#define SCAN_NBLK ((N_NODES + SCAN_CH - 1) / SCAN_CH)

__global__ void scan1_kernel() {
    __shared__ int sh[SCAN_CH];
    int t = threadIdx.x;
    int g = blockIdx.x * SCAN_CH + t;
    int v = (g < N_NODES) ? g_counts[g] : 0;
    sh[t] = v;
    __syncthreads();
    for (int o = 1; o < SCAN_CH; o <<= 1) {
        int x = (t >= o) ? sh[t - o] : 0;
        __syncthreads();
        sh[t] += x;
        __syncthreads();
    }
    if (g < N_NODES) g_offs[g] = sh[t] - v;
    if (t == SCAN_CH - 1) g_bsum[blockIdx.x] = sh[t];
}

__global__ void scan2_kernel() {
    int acc = 0;
    for (int i = 0; i < SCAN_NBLK; i++) {
        g_bsum_ex[i] = acc;
        acc += g_bsum[i];
    }
}

__global__ void scan3_kernel() {
    int g = blockIdx.x * SCAN_CH + threadIdx.x;
    if (g < N_NODES) {
        int v = g_offs[g] + g_bsum_ex[blockIdx.x];
        g_offs[g] = v;
        g_wpos[g] = v;
    }
}

// ---------------- K4: CSR scatter of src ids ----------------
__global__ void scatter_kernel(const int* __restrict__ ei) {
    int e = blockIdx.x * blockDim.x + threadIdx.x;
    if (e >= N_EDGES) return;
    int s = __ldg(&ei[e]);
    int d = __ldg(&ei[N_EDGES + e]);
    int pos = atomicAdd(&g_wpos[d], 1);
    g_csrc[pos] = s;
}

// ---------------- K5: fused logits+softmax+aggregate ----------------
__global__ __launch_bounds__(256)
void fused_node_kernel(const float* __restrict__ att,
                       const float* __restrict__ bias,
                       float* __restrict__ out) {
    int node = blockIdx.x * 8 + (threadIdx.x >> 5);
    if (node >= N_NODES) return;
    int lane = threadIdx.x & 31;
    int beg = g_offs[node];
    int cnt = g_counts[node];

    const float4* xrp = reinterpret_cast<const float4*>(g_xr + (size_t)node * D_OUT);
    const float4* atp = reinterpret_cast<const float4*>(att);
    float4 xr0 = xrp[lane], xr1 = xrp[lane + 32];
    float4 at0 = atp[lane], at1 = atp[lane + 32];

    float4 acc0 = make_float4(0.f, 0.f, 0.f, 0.f);
    float4 acc1 = make_float4(0.f, 0.f, 0.f, 0.f);
    float denom = 0.f;

    int s_reg = (lane < cnt) ? g_csrc[beg + lane] : 0;
    int batch = 0;

    int j = 0;
    for (; j + 2 <= cnt; j += 2) {
        if ((j >> 5) != batch) {
            batch = j >> 5;
            int idx = beg + batch * 32 + lane;
            s_reg = (batch * 32 + lane < cnt) ? g_csrc[idx] : 0;
        }
        int s0 = __shfl_sync(0xffffffffu, s_reg, j & 31);
        int s1;
        if (((j + 1) >> 5) != batch) {
            batch = (j + 1) >> 5;
            int idx = beg + batch * 32 + lane;
            s_reg = (batch * 32 + lane < cnt) ? g_csrc[idx] : 0;
            s1 = __shfl_sync(0xffffffffu, s_reg, (j + 1) & 31);
        } else {
            s1 = __shfl_sync(0xffffffffu, s_reg, (j + 1) & 31);
        }

        const float4* xp0 = reinterpret_cast<const float4*>(g_xl + (size_t)s0 * D_OUT);
        const float4* xp1 = reinterpret_cast<const float4*>(g_xl + (size_t)s1 * D_OUT);
        float4 a0 = xp0[lane], b0 = xp0[lane + 32];
        float4 a1 = xp1[lane], b1 = xp1[lane + 32];

        float p0 = 0.f, p1 = 0.f, h;
        h = a0.x + xr0.x; h = h > 0.f ? h : NEG_SLOPE * h; p0 = fmaf(at0.x, h, p0);
        h = a0.y + xr0.y; h = h > 0.f ? h : NEG_SLOPE * h; p0 = fmaf(at0.y, h, p0);
        h = a0.z + xr0.z; h = h > 0.f ? h : NEG_SLOPE * h; p0 = fmaf(at0.z, h, p0);
        h = a0.w + xr0.w; h = h > 0.f ? h : NEG_SLOPE * h; p0 = fmaf(at0.w, h, p0);
        h = b0.x + xr1.x; h = h > 0.f ? h : NEG_SLOPE * h; p0 = fmaf(at1.x, h, p0);
        h = b0.y + xr1.y; h = h > 0.f ? h : NEG_SLOPE * h; p0 = fmaf(at1.y, h, p0);
        h = b0.z + xr1.z; h = h > 0.f ? h : NEG_SLOPE * h; p0 = fmaf(at1.z, h, p0);
        h = b0.w + xr1.w; h = h > 0.f ? h : NEG_SLOPE * h; p0 = fmaf(at1.w, h, p0);
        h = a1.x + xr0.x; h = h > 0.f ? h : NEG_SLOPE * h; p1 = fmaf(at0.x, h, p1);
        h = a1.y + xr0.y; h = h > 0.f ? h : NEG_SLOPE * h; p1 = fmaf(at0.y, h, p1);
        h = a1.z + xr0.z; h = h > 0.f ? h : NEG_SLOPE * h; p1 = fmaf(at0.z, h, p1);
        h = a1.w + xr0.w; h = h > 0.f ? h : NEG_SLOPE * h; p1 = fmaf(at0.w, h, p1);
        h = b1.x + xr1.x; h = h > 0.f ? h : NEG_SLOPE * h; p1 = fmaf(at1.x, h, p1);
        h = b1.y + xr1.y; h = h > 0.f ? h : NEG_SLOPE * h; p1 = fmaf(at1.y, h, p1);
        h = b1.z + xr1.z; h = h > 0.f ? h : NEG_SLOPE * h; p1 = fmaf(at1.z, h, p1);
        h = b1.w + xr1.w; h = h > 0.f ? h : NEG_SLOPE * h; p1 = fmaf(at1.w, h, p1);

#pragma unroll
        for (int o = 16; o > 0; o >>= 1) {
            p0 += __shfl_xor_sync(0xffffffffu, p0, o);
            p1 += __shfl_xor_sync(0xffffffffu, p1, o);
        }
        float w0 = __expf(p0);
        float w1 = __expf(p1);
        denom += w0 + w1;
        acc0.x = fmaf(w0, a0.x, acc0.x); acc0.y = fmaf(w0, a0.y, acc0.y);
        acc0.z = fmaf(w0, a0.z, acc0.z); acc0.w = fmaf(w0, a0.w, acc0.w);
        acc1.x = fmaf(w0, b0.x, acc1.x); acc1.y = fmaf(w0, b0.y, acc1.y);
        acc1.z = fmaf(w0, b0.z, acc1.z); acc1.w = fmaf(w0, b0.w, acc1.w);
        acc0.x = fmaf(w1, a1.x, acc0.x); acc0.y = fmaf(w1, a1.y, acc0.y);
        acc0.z = fmaf(w1, a1.z, acc0.z); acc0.w = fmaf(w1, a1.w, acc0.w);
        acc1.x = fmaf(w1, b1.x, acc1.x); acc1.y = fmaf(w1, b1.y, acc1.y);
        acc1.z = fmaf(w1, b1.z, acc1.z); acc1.w = fmaf(w1, b1.w, acc1.w);
    }
    if (j < cnt) {
        if ((j >> 5) != batch) {
            batch = j >> 5;
            int idx = beg + batch * 32 + lane;
            s_reg = (batch * 32 + lane < cnt) ? g_csrc[idx] : 0;
        }
        int s0 = __shfl_sync(0xffffffffu, s_reg, j & 31);
        const float4* xp0 = reinterpret_cast<const float4*>(g_xl + (size_t)s0 * D_OUT);
        float4 a0 = xp0[lane], b0 = xp0[lane + 32];
        float p0 = 0.f, h;
        h = a0.x + xr0.x; h = h > 0.f ? h : NEG_SLOPE * h; p0 = fmaf(at0.x, h, p0);
        h = a0.y + xr0.y; h = h > 0.f ? h : NEG_SLOPE * h; p0 = fmaf(at0.y, h, p0);
        h = a0.z + xr0.z; h = h > 0.f ? h : NEG_SLOPE * h; p0 = fmaf(at0.z, h, p0);
        h = a0.w + xr0.w; h = h > 0.f ? h : NEG_SLOPE * h; p0 = fmaf(at0.w, h, p0);
        h = b0.x + xr1.x; h = h > 0.f ? h : NEG_SLOPE * h; p0 = fmaf(at1.x, h, p0);
        h = b0.y + xr1.y; h = h > 0.f ? h : NEG_SLOPE * h; p0 = fmaf(at1.y, h, p0);
        h = b0.z + xr1.z; h = h > 0.f ? h : NEG_SLOPE * h; p0 = fmaf(at1.z, h, p0);
        h = b0.w + xr1.w; h = h > 0.f ? h : NEG_SLOPE * h; p0 = fmaf(at1.w, h, p0);
#pragma unroll
        for (int o = 16; o > 0; o >>= 1) p0 += __shfl_xor_sync(0xffffffffu, p0, o);
        float w0 = __expf(p0);
        denom += w0;
        acc0.x = fmaf(w0, a0.x, acc0.x); acc0.y = fmaf(w0, a0.y, acc0.y);
        acc0.z = fmaf(w0, a0.z, acc0.z); acc0.w = fmaf(w0, a0.w, acc0.w);
        acc1.x = fmaf(w0, b0.x, acc1.x); acc1.y = fmaf(w0, b0.y, acc1.y);
        acc1.z = fmaf(w0, b0.z, acc1.z); acc1.w = fmaf(w0, b0.w, acc1.w);
    }

    float rd = 1.f / (denom + 1e-16f);
    const float4* bi = reinterpret_cast<const float4*>(bias);
    float4 bb0 = bi[lane], bb1 = bi[lane + 32];
    float4 o0 = make_float4(fmaf(acc0.x, rd, bb0.x), fmaf(acc0.y, rd, bb0.y),
                            fmaf(acc0.z, rd, bb0.z), fmaf(acc0.w, rd, bb0.w));
    float4 o1 = make_float4(fmaf(acc1.x, rd, bb1.x), fmaf(acc1.y, rd, bb1.y),
                            fmaf(acc1.z, rd, bb1.z), fmaf(acc1.w, rd, bb1.w));
    float4* op = reinterpret_cast<float4*>(out + (size_t)node * D_OUT);
    op[lane]      = o0;
    op[lane + 32] = o1;
}

// ---------------- launch ----------------
extern "C" void kernel_launch(void* const* d_in, const int* in_sizes, int n_in,
                              void* d_out, int out_size) {
    const float* x    = (const float*)d_in[0];
    const int*   ei   = (const int*)d_in[1];
    const float* W_l  = (const float*)d_in[2];
    const float* b_l  = (const float*)d_in[3];
    const float* W_r  = (const float*)d_in[4];
    const float* b_r  = (const float*)d_in[5];
    const float* att  = (const float*)d_in[6];
    const float* bias = (const float*)d_in[7];
    float* out = (float*)d_out;

    init_kernel<<<(N_NODES + 255) / 256, 256>>>();
    hist_kernel<<<(N_EDGES + 255) / 256, 256>>>(ei);

    dim3 ggrid(2 * D_OUT / GBN, (N_NODES + GBM - 1) / GBM);   // (4, 782)
    gemm_fp16_kernel<<<ggrid, 256>>>(x, W_l, b_l, W_r, b_r);

    scan1_kernel<<<SCAN_NBLK, SCAN_CH>>>();
    scan2_kernel<<<1, 1>>>();
    scan3_kernel<<<SCAN_NBLK, SCAN_CH>>>();

    scatter_kernel<<<(N_EDGES + 255) / 256, 256>>>(ei);

    fused_node_kernel<<<(N_NODES + 7) / 8, 256>>>(att, bias, out);
}